// round 1
// baseline (speedup 1.0000x reference)
#include <cuda_runtime.h>
#include <cuda_bf16.h>

#define EMBED 100
#define BATCH 8192
#define VEC4_PER_MAT 2500   // 100*100/4
#define F4_PER_ROW   25     // 100/4
#define NTHREADS     256

__global__ __launch_bounds__(NTHREADS)
void matrix_skipgram_kernel(const int* __restrict__ X_argument,
                            const int* __restrict__ X_functor,
                            const int* __restrict__ X_context,
                            const float* __restrict__ noun_matrix,
                            const float* __restrict__ functor_table,
                            const float* __restrict__ context_table,
                            float* __restrict__ out)
{
    const int b = blockIdx.x;
    const int t = threadIdx.x;

    __shared__ float s_arg[EMBED];
    __shared__ float s_ctx[EMBED];
    __shared__ float s_red[NTHREADS / 32];

    // Stage argument and context vectors
    {
        const float* av = noun_matrix   + (size_t)X_argument[b] * EMBED;
        const float* cv = context_table + (size_t)X_context[b]  * EMBED;
        if (t < EMBED) {
            s_arg[t] = av[t];
            s_ctx[t] = cv[t];
        }
    }
    __syncthreads();

    // Stream the 100x100 functor matrix as coalesced float4 loads.
    // Row length 100 floats = 25 float4; row base = idx*40000 B (16B aligned).
    const float4* __restrict__ M =
        reinterpret_cast<const float4*>(functor_table + (size_t)X_functor[b] * (EMBED * EMBED));

    float acc = 0.0f;
    #pragma unroll 4
    for (int k = t; k < VEC4_PER_MAT; k += NTHREADS) {
        const int i  = k / F4_PER_ROW;            // row (context index)
        const int j4 = (k - i * F4_PER_ROW) * 4;  // starting column
        const float4 m = M[k];
        const float c = s_ctx[i];
        float dot = m.x * s_arg[j4]
                  + m.y * s_arg[j4 + 1]
                  + m.z * s_arg[j4 + 2]
                  + m.w * s_arg[j4 + 3];
        acc = fmaf(c, dot, acc);
    }

    // Warp reduction
    #pragma unroll
    for (int o = 16; o > 0; o >>= 1)
        acc += __shfl_xor_sync(0xFFFFFFFFu, acc, o);

    if ((t & 31) == 0)
        s_red[t >> 5] = acc;
    __syncthreads();

    if (t < (NTHREADS / 32)) {
        acc = s_red[t];
        #pragma unroll
        for (int o = (NTHREADS / 64); o > 0; o >>= 1)
            acc += __shfl_xor_sync(0xFFu, acc, o);
        if (t == 0)
            out[b] = acc;
    }
}

extern "C" void kernel_launch(void* const* d_in, const int* in_sizes, int n_in,
                              void* d_out, int out_size)
{
    const int*   X_argument    = (const int*)  d_in[0];
    const int*   X_functor     = (const int*)  d_in[1];
    const int*   X_context     = (const int*)  d_in[2];
    const float* noun_matrix   = (const float*)d_in[3];
    const float* functor_table = (const float*)d_in[4];
    const float* context_table = (const float*)d_in[5];
    float* out = (float*)d_out;

    matrix_skipgram_kernel<<<BATCH, NTHREADS>>>(
        X_argument, X_functor, X_context,
        noun_matrix, functor_table, context_table, out);
}